// round 5
// baseline (speedup 1.0000x reference)
#include <cuda_runtime.h>

#define C 66
#define START_TAG 64
#define STOP_TAG 65
#define NB 32
#define LL 1024
#define DD 1024
#define IMPOSSIBLE_F -10000.0f
#define L2E 1.4426950408889634f
#define LN2F 0.6931471805599453f

// scratch: emissions [B*L, 66] fp32 (8.65 MB)
__device__ float g_feats[(size_t)NB * LL * C];
// 1 if ys is int64 (high words all zero), 0 if int32
__device__ int g_is64;

// ---------------------------------------------------------------------------
// Detect ys dtype. Reads only the first NB*LL int32 words (in-bounds for both
// int32 [NB*LL words] and int64 [2*NB*LL words] interpretations). Tags are in
// [0,64), so if the data is int64 every odd word (high word) is 0; if int32,
// odd words are random tags whose OR is nonzero w.p. ~1.
// ---------------------------------------------------------------------------
__global__ void detect_kernel(const int* __restrict__ ys32)
{
    __shared__ int acc_s;
    if (threadIdx.x == 0) acc_s = 0;
    __syncthreads();
    int v = 0;
    for (int t = threadIdx.x; t < (NB * LL) / 2; t += 256) v |= ys32[2 * t + 1];
    #pragma unroll
    for (int o = 16; o; o >>= 1) v |= __shfl_xor_sync(0xffffffffu, v, o);
    if ((threadIdx.x & 31) == 0) atomicOr(&acc_s, v);
    __syncthreads();
    if (threadIdx.x == 0) g_is64 = (acc_s == 0) ? 1 : 0;
}

// ---------------------------------------------------------------------------
// GEMM: feats[m, c] = sum_k A[m,k] * W[k,c] + bias[c]
// A: [32768, 1024] row-major, W: [1024, 66] row-major.
// CTA: 128 rows x all 66 cols, K-tiles of 32, register double-buffered loads.
// Threads 256 = 32(mt) x 8(nt); per-thread tile 4 rows x 9 cols (72-col pad).
// ---------------------------------------------------------------------------
__global__ void __launch_bounds__(256, 2) gemm_kernel(
    const float* __restrict__ A, const float* __restrict__ W,
    const float* __restrict__ bias)
{
    __shared__ float Asm[32][128];   // [k][m]
    __shared__ float Bsm[32][72];    // [k][c], padded to 72

    const int tid = threadIdx.x;
    const int nt = tid & 7;
    const int mt = tid >> 3;
    const int blockRow = blockIdx.x * 128;
    const int row_l = tid & 127;
    const int half = tid >> 7;
    const float* aBase = A + (size_t)(blockRow + row_l) * DD + half * 16;

    // B-load assignment: 32*66 = 2112 contiguous floats per K-tile
    int soff[9]; int gok[9];
    #pragma unroll
    for (int s = 0; s < 9; ++s) {
        int idx = tid + 256 * s;
        gok[s] = (idx < 2112);
        int k = idx / 66, c = idx - k * 66;
        soff[s] = k * 72 + c;
    }

    float4 areg[4];
    float breg[9];
    float acc[4][9];
    #pragma unroll
    for (int r = 0; r < 4; ++r)
        #pragma unroll
        for (int j = 0; j < 9; ++j) acc[r][j] = 0.f;

    // prefetch K-tile 0
    #pragma unroll
    for (int i = 0; i < 4; ++i) areg[i] = *(const float4*)(aBase + i * 4);
    #pragma unroll
    for (int s = 0; s < 9; ++s) breg[s] = gok[s] ? W[tid + 256 * s] : 0.f;

    for (int kt = 0; kt < 32; ++kt) {
        __syncthreads();
        #pragma unroll
        for (int i = 0; i < 4; ++i) {
            Asm[half * 16 + i * 4 + 0][row_l] = areg[i].x;
            Asm[half * 16 + i * 4 + 1][row_l] = areg[i].y;
            Asm[half * 16 + i * 4 + 2][row_l] = areg[i].z;
            Asm[half * 16 + i * 4 + 3][row_l] = areg[i].w;
        }
        {
            float* bflat = &Bsm[0][0];
            #pragma unroll
            for (int s = 0; s < 9; ++s) if (gok[s]) bflat[soff[s]] = breg[s];
        }
        __syncthreads();

        if (kt + 1 < 32) {  // prefetch next tile into registers
            const float* a2 = aBase + (kt + 1) * 32;
            #pragma unroll
            for (int i = 0; i < 4; ++i) areg[i] = *(const float4*)(a2 + i * 4);
            const float* w2 = W + (kt + 1) * 2112;
            #pragma unroll
            for (int s = 0; s < 9; ++s) if (gok[s]) breg[s] = w2[tid + 256 * s];
        }

        #pragma unroll 8
        for (int k = 0; k < 32; ++k) {
            float4 av = *(const float4*)&Asm[k][mt * 4];
            float a0 = av.x, a1 = av.y, a2v = av.z, a3 = av.w;
            float bj[9];
            #pragma unroll
            for (int j = 0; j < 9; ++j) bj[j] = Bsm[k][nt * 9 + j];
            #pragma unroll
            for (int j = 0; j < 9; ++j) {
                acc[0][j] = fmaf(a0,  bj[j], acc[0][j]);
                acc[1][j] = fmaf(a1,  bj[j], acc[1][j]);
                acc[2][j] = fmaf(a2v, bj[j], acc[2][j]);
                acc[3][j] = fmaf(a3,  bj[j], acc[3][j]);
            }
        }
    }

    #pragma unroll
    for (int j = 0; j < 9; ++j) {
        int c = nt * 9 + j;
        if (c < C) {
            float bc = bias[c];
            #pragma unroll
            for (int r = 0; r < 4; ++r) {
                size_t row = (size_t)(blockRow + mt * 4 + r);
                g_feats[row * C + c] = acc[r][j] + bc;
            }
        }
    }
}

// ---------------------------------------------------------------------------
// CRF forward recursion. One CTA per batch. 288 threads: tag i = tid>>2,
// lane-quad q = tid&3 splits the 66-wide dot into 17-FMA chunks + 2 shfl.
// Factored lse: E_ij = exp(T_ij) precomputed once; p_j = exp(s_j - m_stale);
// s_i' = log(sum_j E_ij p_j) + m_stale + emit_i. m_stale = s_0 from two
// steps ago (bounded drift, f32-safe). One __syncthreads per step via
// double-buffered p/m.
// ---------------------------------------------------------------------------
__global__ void __launch_bounds__(288, 1) forward_kernel(
    const float* __restrict__ masks, const float* __restrict__ trans,
    float* __restrict__ out)
{
    const int b = blockIdx.x;
    const int tid = threadIdx.x;
    const int i = tid >> 2;
    const int q = tid & 3;
    const bool lead = (q == 0) && (i < C);

    __shared__ float p_sm[2][68];
    __shared__ float m_sm[2];

    float E[17];
    const int j0 = q * 17;
    #pragma unroll
    for (int jj = 0; jj < 17; ++jj) {
        int j = j0 + jj;
        E[jj] = (i < C && j < C) ? expf(trans[i * C + j]) : 0.f;
    }

    float s = (i == START_TAG) ? 0.f : IMPOSSIBLE_F;
    float m = 0.f;
    if (tid == 0) {
        m_sm[0] = 0.f; m_sm[1] = 0.f;
        p_sm[0][66] = p_sm[0][67] = 0.f;
        p_sm[1][66] = p_sm[1][67] = 0.f;
    }

    const float* fb = g_feats + (size_t)b * LL * C;
    const float* mb = masks + (size_t)b * LL;
    float e0 = 0.f, e1 = 0.f, mk0 = 1.f, mk1 = 1.f;
    if (lead) { e0 = fb[i]; e1 = fb[C + i]; mk0 = mb[0]; mk1 = mb[1]; }

    int buf = 0;
    for (int t = 0; t < LL; ++t) {
        if (lead) p_sm[buf][i] = exp2f((s - m) * L2E);
        __syncthreads();
        float m_next = m_sm[buf];
        // prefetch emissions/mask for t+2
        float e2 = 0.f, mk2 = 1.f;
        if (lead && t + 2 < LL) { e2 = fb[(size_t)(t + 2) * C + i]; mk2 = mb[t + 2]; }

        const float* pp = &p_sm[buf][j0];
        float acc0 = 0.f, acc1 = 0.f;
        #pragma unroll
        for (int jj = 0; jj < 17; jj += 2) acc0 = fmaf(E[jj], pp[jj], acc0);
        #pragma unroll
        for (int jj = 1; jj < 17; jj += 2) acc1 = fmaf(E[jj], pp[jj], acc1);
        float acc = acc0 + acc1;
        acc += __shfl_xor_sync(0xffffffffu, acc, 1);
        acc += __shfl_xor_sync(0xffffffffu, acc, 2);

        if (lead) {
            float snew = __log2f(acc) * LN2F + m + e0;
            s = (mk0 != 0.f) ? snew : s;
            if (i == 0) m_sm[buf ^ 1] = s;   // stale max source for step t+2
            e0 = e1; e1 = e2; mk0 = mk1; mk1 = mk2;
        }
        m = m_next;
        buf ^= 1;
    }

    __syncthreads();
    if (lead) p_sm[0][i] = s + trans[STOP_TAG * C + i];
    __syncthreads();
    if (tid == 0) {
        float mx = -3.4e38f;
        for (int k = 0; k < C; ++k) mx = fmaxf(mx, p_sm[0][k]);
        float sum = 0.f;
        for (int k = 0; k < C; ++k) sum += exp2f((p_sm[0][k] - mx) * L2E);
        out[b] = __log2f(sum) * LN2F + mx;
    }
}

// ---------------------------------------------------------------------------
// Gold path score. One CTA per batch. ys dtype-agnostic via g_is64.
// ---------------------------------------------------------------------------
__global__ void __launch_bounds__(256, 1) gold_kernel(
    const int* __restrict__ ys32, const float* __restrict__ masks,
    const float* __restrict__ trans, float* __restrict__ out)
{
    const int b = blockIdx.x;
    const int tid = threadIdx.x;
    const int stride = g_is64 ? 2 : 1;           // int32 words per element
    const int* yb = ys32 + (size_t)b * LL * stride;
    const float* mb = masks + (size_t)b * LL;

    float local = 0.f, mloc = 0.f;
    for (int t = tid; t < LL; t += 256) {
        int y  = yb[t * stride];
        int yp = t ? yb[(t - 1) * stride] : START_TAG;
        y  = min(max(y,  0), C - 1);             // defensive clamp
        yp = min(max(yp, 0), C - 1);
        float mk = mb[t];
        local += (trans[y * C + yp] + g_feats[((size_t)b * LL + t) * C + y]) * mk;
        mloc += mk;
    }
    #pragma unroll
    for (int o = 16; o; o >>= 1) {
        local += __shfl_xor_sync(0xffffffffu, local, o);
        mloc  += __shfl_xor_sync(0xffffffffu, mloc,  o);
    }
    __shared__ float s1[8], s2[8];
    int w = tid >> 5;
    if ((tid & 31) == 0) { s1[w] = local; s2[w] = mloc; }
    __syncthreads();
    if (tid == 0) {
        float tot = 0.f, ms = 0.f;
        #pragma unroll
        for (int k = 0; k < 8; ++k) { tot += s1[k]; ms += s2[k]; }
        int len = (int)(ms + 0.5f);
        int last = (len > 0) ? yb[(len - 1) * stride] : START_TAG;
        last = min(max(last, 0), C - 1);
        out[NB + b] = tot + trans[STOP_TAG * C + last];
    }
}

extern "C" void kernel_launch(void* const* d_in, const int* in_sizes, int n_in,
                              void* d_out, int out_size)
{
    const float* features = (const float*)d_in[0];
    const int*   ys32     = (const int*)d_in[1];
    const float* masks    = (const float*)d_in[2];
    const float* fc_w     = (const float*)d_in[3];
    const float* fc_b     = (const float*)d_in[4];
    const float* trans    = (const float*)d_in[5];
    float* out = (float*)d_out;

    detect_kernel<<<1, 256>>>(ys32);
    gemm_kernel<<<256, 256>>>(features, fc_w, fc_b);
    forward_kernel<<<NB, 288>>>(masks, trans, out);
    gold_kernel<<<NB, 256>>>(ys32, masks, trans, out);
}

// round 6
// speedup vs baseline: 1.0320x; 1.0320x over previous
#include <cuda_runtime.h>

#define C 66            // full tagset incl START/STOP (trans stride)
#define CT 64           // tracked tags (START/STOP provably inert)
#define START_TAG 64
#define STOP_TAG 65
#define NB 32
#define LL 1024
#define DD 1024
#define IMPOSSIBLE_F -10000.0f
#define L2E 1.4426950408889634f
#define LN2F 0.6931471805599453f

// scratch: emissions [B*L, 64] fp32 (8.4 MB)
__device__ float g_feats[(size_t)NB * LL * CT];
// 1 if ys is int64 (high words all zero), 0 if int32
__device__ int g_is64;

// ---------------------------------------------------------------------------
// Detect ys dtype (reads only first NB*LL int32 words; in-bounds either way).
// ---------------------------------------------------------------------------
__global__ void detect_kernel(const int* __restrict__ ys32)
{
    __shared__ int acc_s;
    if (threadIdx.x == 0) acc_s = 0;
    __syncthreads();
    int v = 0;
    for (int t = threadIdx.x; t < (NB * LL) / 2; t += 256) v |= ys32[2 * t + 1];
    #pragma unroll
    for (int o = 16; o; o >>= 1) v |= __shfl_xor_sync(0xffffffffu, v, o);
    if ((threadIdx.x & 31) == 0) atomicOr(&acc_s, v);
    __syncthreads();
    if (threadIdx.x == 0) g_is64 = (acc_s == 0) ? 1 : 0;
}

// ---------------------------------------------------------------------------
// GEMM: feats[m, c] = sum_k A[m,k] * W[k,c] + bias[c], c in [0,64).
// A: [32768,1024] row-major, W: [1024,66] row-major (cols 0..63 used).
// CTA: 128 rows x 64 cols, K-tiles of 32, register double-buffered loads.
// 256 thr = 32(mt) x 8(nt); per-thread 4 rows x 8 cols.
// ---------------------------------------------------------------------------
__global__ void __launch_bounds__(256, 2) gemm_kernel(
    const float* __restrict__ A, const float* __restrict__ W,
    const float* __restrict__ bias)
{
    __shared__ float Asm[32][128];   // [k][m]
    __shared__ float Bsm[32][68];    // [k][c], pad 4

    const int tid = threadIdx.x;
    const int nt = tid & 7;
    const int mt = tid >> 3;
    const int blockRow = blockIdx.x * 128;
    const int row_l = tid & 127;
    const int half = tid >> 7;
    const float* aBase = A + (size_t)(blockRow + row_l) * DD + half * 16;

    // B-load assignment: 32x64 = 2048 = 8 loads of 256 (W has stride 66)
    int kk[8], cc[8];
    #pragma unroll
    for (int s = 0; s < 8; ++s) {
        int idx = tid + 256 * s;
        kk[s] = idx >> 6;
        cc[s] = idx & 63;
    }

    float4 areg[4];
    float breg[8];
    float acc[4][8];
    #pragma unroll
    for (int r = 0; r < 4; ++r)
        #pragma unroll
        for (int j = 0; j < 8; ++j) acc[r][j] = 0.f;

    // prefetch K-tile 0
    #pragma unroll
    for (int i = 0; i < 4; ++i) areg[i] = *(const float4*)(aBase + i * 4);
    #pragma unroll
    for (int s = 0; s < 8; ++s) breg[s] = W[kk[s] * C + cc[s]];

    for (int kt = 0; kt < 32; ++kt) {
        __syncthreads();
        #pragma unroll
        for (int i = 0; i < 4; ++i) {
            Asm[half * 16 + i * 4 + 0][row_l] = areg[i].x;
            Asm[half * 16 + i * 4 + 1][row_l] = areg[i].y;
            Asm[half * 16 + i * 4 + 2][row_l] = areg[i].z;
            Asm[half * 16 + i * 4 + 3][row_l] = areg[i].w;
        }
        #pragma unroll
        for (int s = 0; s < 8; ++s) Bsm[kk[s]][cc[s]] = breg[s];
        __syncthreads();

        if (kt + 1 < 32) {  // prefetch next tile into registers
            const float* a2 = aBase + (kt + 1) * 32;
            #pragma unroll
            for (int i = 0; i < 4; ++i) areg[i] = *(const float4*)(a2 + i * 4);
            const float* w2 = W + (size_t)(kt + 1) * 32 * C;
            #pragma unroll
            for (int s = 0; s < 8; ++s) breg[s] = w2[kk[s] * C + cc[s]];
        }

        #pragma unroll 8
        for (int k = 0; k < 32; ++k) {
            float4 av = *(const float4*)&Asm[k][mt * 4];
            float a0 = av.x, a1 = av.y, a2v = av.z, a3 = av.w;
            float4 b0 = *(const float4*)&Bsm[k][nt * 8];
            float4 b1 = *(const float4*)&Bsm[k][nt * 8 + 4];
            float bj[8] = {b0.x, b0.y, b0.z, b0.w, b1.x, b1.y, b1.z, b1.w};
            #pragma unroll
            for (int j = 0; j < 8; ++j) {
                acc[0][j] = fmaf(a0,  bj[j], acc[0][j]);
                acc[1][j] = fmaf(a1,  bj[j], acc[1][j]);
                acc[2][j] = fmaf(a2v, bj[j], acc[2][j]);
                acc[3][j] = fmaf(a3,  bj[j], acc[3][j]);
            }
        }
    }

    float4 bb0, bb1;
    bb0.x = bias[nt * 8 + 0]; bb0.y = bias[nt * 8 + 1];
    bb0.z = bias[nt * 8 + 2]; bb0.w = bias[nt * 8 + 3];
    bb1.x = bias[nt * 8 + 4]; bb1.y = bias[nt * 8 + 5];
    bb1.z = bias[nt * 8 + 6]; bb1.w = bias[nt * 8 + 7];
    #pragma unroll
    for (int r = 0; r < 4; ++r) {
        size_t row = (size_t)(blockRow + mt * 4 + r);
        float4 o0, o1;
        o0.x = acc[r][0] + bb0.x; o0.y = acc[r][1] + bb0.y;
        o0.z = acc[r][2] + bb0.z; o0.w = acc[r][3] + bb0.w;
        o1.x = acc[r][4] + bb1.x; o1.y = acc[r][5] + bb1.y;
        o1.z = acc[r][6] + bb1.z; o1.w = acc[r][7] + bb1.w;
        *(float4*)&g_feats[row * CT + nt * 8]     = o0;
        *(float4*)&g_feats[row * CT + nt * 8 + 4] = o1;
    }
}

// ---------------------------------------------------------------------------
// CRF forward (64x64 reduced dynamics) + fused gold score.
// One CTA per batch, 160 threads: warps 0-3 run the recursion (tag i=tid>>1,
// half q=tid&1: 32-wide dot each + 1 shfl), warp 4 computes the gold score.
// Step 0 folded analytically: s_i = T[i,START] + emit_0[i]. Steps 1..1023 use
// only the 64x64 block of exp(T) (START col / STOP row provably inert in f32).
// Factored lse with 2-step-stale max (m = s_0 from two steps back); one named
// barrier (128 threads) per step, double-buffered p / m.
// ---------------------------------------------------------------------------
__global__ void __launch_bounds__(160, 1) forward_kernel(
    const float* __restrict__ masks, const float* __restrict__ trans,
    const int* __restrict__ ys32, float* __restrict__ out)
{
    const int b = blockIdx.x;
    const int tid = threadIdx.x;

    __shared__ float p_sm[2][CT];
    __shared__ float m_sm[2];

    // ---------------- gold warp ----------------
    if (tid >= 128) {
        const int l = tid - 128;
        const int stride = g_is64 ? 2 : 1;
        const int* yb = ys32 + (size_t)b * LL * stride;
        const float* mb = masks + (size_t)b * LL;
        float local = 0.f, mloc = 0.f;
        for (int t = l; t < LL; t += 32) {
            int y  = yb[t * stride];
            int yp = t ? yb[(t - 1) * stride] : START_TAG;
            y  = min(max(y,  0), CT - 1);
            yp = min(max(yp, 0), C - 1);
            float mk = mb[t];
            local += (trans[y * C + yp] + g_feats[((size_t)b * LL + t) * CT + y]) * mk;
            mloc  += mk;
        }
        #pragma unroll
        for (int o = 16; o; o >>= 1) {
            local += __shfl_xor_sync(0xffffffffu, local, o);
            mloc  += __shfl_xor_sync(0xffffffffu, mloc,  o);
        }
        if (l == 0) {
            int len = (int)(mloc + 0.5f);
            int last = (len > 0) ? yb[(len - 1) * stride] : START_TAG;
            last = min(max(last, 0), C - 1);
            out[NB + b] = local + trans[STOP_TAG * C + last];
        }
        return;
    }

    // ---------------- recursion warps ----------------
    const int i = tid >> 1;     // tag 0..63
    const int q = tid & 1;      // half
    const int j0 = q * 32;

    float E[32];
    #pragma unroll
    for (int jj = 0; jj < 32; ++jj)
        E[jj] = expf(trans[i * C + (j0 + jj)]);

    const float* fb = g_feats + (size_t)b * LL * CT;
    const float* mb = masks + (size_t)b * LL;

    // fold step 0: s_i = T[i,START] + emit_0[i]  (mask_0-guarded)
    float s;
    {
        float mk = mb[0];
        s = (mk != 0.f) ? (trans[i * C + START_TAG] + fb[i]) : IMPOSSIBLE_F;
    }
    float m = 0.f;
    if (tid == 0) { m_sm[0] = 0.f; m_sm[1] = 0.f; }

    // rolling emission/mask pipeline for t = 1,2
    float e0 = fb[CT + i], e1 = fb[2 * CT + i];
    float mk0 = mb[1], mk1 = mb[2];

    int buf = 0;
    for (int t = 1; t < LL; ++t) {
        if (q == 0) p_sm[buf][i] = exp2f((s - m) * L2E);
        asm volatile("bar.sync 1, 128;" ::: "memory");
        float m_next = m_sm[buf];

        // prefetch t+2
        float e2 = 0.f, mk2 = 1.f;
        if (t + 2 < LL) { e2 = fb[(size_t)(t + 2) * CT + i]; mk2 = mb[t + 2]; }

        const float* pp = &p_sm[buf][j0];
        float a0 = 0.f, a1 = 0.f, a2 = 0.f, a3 = 0.f;
        #pragma unroll
        for (int jj = 0; jj < 32; jj += 4) {
            a0 = fmaf(E[jj + 0], pp[jj + 0], a0);
            a1 = fmaf(E[jj + 1], pp[jj + 1], a1);
            a2 = fmaf(E[jj + 2], pp[jj + 2], a2);
            a3 = fmaf(E[jj + 3], pp[jj + 3], a3);
        }
        float acc = (a0 + a1) + (a2 + a3);
        acc += __shfl_xor_sync(0xffffffffu, acc, 1);

        float snew = __log2f(acc) * LN2F + m + e0;
        s = (mk0 != 0.f) ? snew : s;
        if (tid == 0) m_sm[buf ^ 1] = s;   // stale max for step t+2
        e0 = e1; e1 = e2; mk0 = mk1; mk1 = mk2;
        m = m_next;
        buf ^= 1;
    }

    // final: lse_i (s_i + T[STOP,i])
    if (q == 0) p_sm[0][i] = s + trans[STOP_TAG * C + i];
    asm volatile("bar.sync 1, 128;" ::: "memory");
    if (tid < 32) {
        float v0 = p_sm[0][tid], v1 = p_sm[0][tid + 32];
        float mx = fmaxf(v0, v1);
        #pragma unroll
        for (int o = 16; o; o >>= 1) mx = fmaxf(mx, __shfl_xor_sync(0xffffffffu, mx, o));
        float sum = exp2f((v0 - mx) * L2E) + exp2f((v1 - mx) * L2E);
        #pragma unroll
        for (int o = 16; o; o >>= 1) sum += __shfl_xor_sync(0xffffffffu, sum, o);
        if (tid == 0) out[b] = __log2f(sum) * LN2F + mx;
    }
}

extern "C" void kernel_launch(void* const* d_in, const int* in_sizes, int n_in,
                              void* d_out, int out_size)
{
    const float* features = (const float*)d_in[0];
    const int*   ys32     = (const int*)d_in[1];
    const float* masks    = (const float*)d_in[2];
    const float* fc_w     = (const float*)d_in[3];
    const float* fc_b     = (const float*)d_in[4];
    const float* trans    = (const float*)d_in[5];
    float* out = (float*)d_out;

    detect_kernel<<<1, 256>>>(ys32);
    gemm_kernel<<<256, 256>>>(features, fc_w, fc_b);
    forward_kernel<<<NB, 160>>>(masks, trans, ys32, out);
}

// round 8
// speedup vs baseline: 1.4534x; 1.4084x over previous
#include <cuda_runtime.h>

#define C 66            // full tagset incl START/STOP (trans stride)
#define CT 64           // tracked tags (START/STOP provably inert)
#define START_TAG 64
#define STOP_TAG 65
#define NB 32
#define LL 1024
#define DD 1024
#define IMPOSSIBLE_F -10000.0f
#define L2E 1.4426950408889634f
#define LN2F 0.6931471805599453f

// scratch: emissions [B*L, 64] fp32 (8.4 MB)
__device__ float g_feats[(size_t)NB * LL * CT];

#define CP_ASYNC16(dst_u32, src_ptr) \
    asm volatile("cp.async.ca.shared.global [%0], [%1], 16;\n" \
                 :: "r"(dst_u32), "l"(src_ptr))
#define CP_COMMIT() asm volatile("cp.async.commit_group;\n" ::: "memory")
#define CP_WAIT6()  asm volatile("cp.async.wait_group 6;\n" ::: "memory")

// ---------------------------------------------------------------------------
// GEMM: feats[m, c] = sum_k A[m,k] * W[k,c] + bias[c], c in [0,64).
// (unchanged from round 6 — validated, ~near FFMA floor for SIMT)
// ---------------------------------------------------------------------------
__global__ void __launch_bounds__(256, 2) gemm_kernel(
    const float* __restrict__ A, const float* __restrict__ W,
    const float* __restrict__ bias)
{
    __shared__ float Asm[32][128];   // [k][m]
    __shared__ float Bsm[32][68];    // [k][c], pad 4

    const int tid = threadIdx.x;
    const int nt = tid & 7;
    const int mt = tid >> 3;
    const int blockRow = blockIdx.x * 128;
    const int row_l = tid & 127;
    const int half = tid >> 7;
    const float* aBase = A + (size_t)(blockRow + row_l) * DD + half * 16;

    int kk[8], cc[8];
    #pragma unroll
    for (int s = 0; s < 8; ++s) {
        int idx = tid + 256 * s;
        kk[s] = idx >> 6;
        cc[s] = idx & 63;
    }

    float4 areg[4];
    float breg[8];
    float acc[4][8];
    #pragma unroll
    for (int r = 0; r < 4; ++r)
        #pragma unroll
        for (int j = 0; j < 8; ++j) acc[r][j] = 0.f;

    #pragma unroll
    for (int i = 0; i < 4; ++i) areg[i] = *(const float4*)(aBase + i * 4);
    #pragma unroll
    for (int s = 0; s < 8; ++s) breg[s] = W[kk[s] * C + cc[s]];

    for (int kt = 0; kt < 32; ++kt) {
        __syncthreads();
        #pragma unroll
        for (int i = 0; i < 4; ++i) {
            Asm[half * 16 + i * 4 + 0][row_l] = areg[i].x;
            Asm[half * 16 + i * 4 + 1][row_l] = areg[i].y;
            Asm[half * 16 + i * 4 + 2][row_l] = areg[i].z;
            Asm[half * 16 + i * 4 + 3][row_l] = areg[i].w;
        }
        #pragma unroll
        for (int s = 0; s < 8; ++s) Bsm[kk[s]][cc[s]] = breg[s];
        __syncthreads();

        if (kt + 1 < 32) {
            const float* a2 = aBase + (kt + 1) * 32;
            #pragma unroll
            for (int i = 0; i < 4; ++i) areg[i] = *(const float4*)(a2 + i * 4);
            const float* w2 = W + (size_t)(kt + 1) * 32 * C;
            #pragma unroll
            for (int s = 0; s < 8; ++s) breg[s] = w2[kk[s] * C + cc[s]];
        }

        #pragma unroll 8
        for (int k = 0; k < 32; ++k) {
            float4 av = *(const float4*)&Asm[k][mt * 4];
            float a0 = av.x, a1 = av.y, a2v = av.z, a3 = av.w;
            float4 b0 = *(const float4*)&Bsm[k][nt * 8];
            float4 b1 = *(const float4*)&Bsm[k][nt * 8 + 4];
            float bj[8] = {b0.x, b0.y, b0.z, b0.w, b1.x, b1.y, b1.z, b1.w};
            #pragma unroll
            for (int j = 0; j < 8; ++j) {
                acc[0][j] = fmaf(a0,  bj[j], acc[0][j]);
                acc[1][j] = fmaf(a1,  bj[j], acc[1][j]);
                acc[2][j] = fmaf(a2v, bj[j], acc[2][j]);
                acc[3][j] = fmaf(a3,  bj[j], acc[3][j]);
            }
        }
    }

    float4 bb0, bb1;
    bb0.x = bias[nt * 8 + 0]; bb0.y = bias[nt * 8 + 1];
    bb0.z = bias[nt * 8 + 2]; bb0.w = bias[nt * 8 + 3];
    bb1.x = bias[nt * 8 + 4]; bb1.y = bias[nt * 8 + 5];
    bb1.z = bias[nt * 8 + 6]; bb1.w = bias[nt * 8 + 7];
    #pragma unroll
    for (int r = 0; r < 4; ++r) {
        size_t row = (size_t)(blockRow + mt * 4 + r);
        float4 o0, o1;
        o0.x = acc[r][0] + bb0.x; o0.y = acc[r][1] + bb0.y;
        o0.z = acc[r][2] + bb0.z; o0.w = acc[r][3] + bb0.w;
        o1.x = acc[r][4] + bb1.x; o1.y = acc[r][5] + bb1.y;
        o1.z = acc[r][6] + bb1.z; o1.w = acc[r][7] + bb1.w;
        *(float4*)&g_feats[row * CT + nt * 8]     = o0;
        *(float4*)&g_feats[row * CT + nt * 8 + 4] = o1;
    }
}

// ---------------------------------------------------------------------------
// CRF forward in probability space + fused gold score.
// One CTA per batch, 160 threads. Warps 0-3: recursion over 64 tags
// (tag i = tid>>1, half q = tid&1 does a 32-wide dot + 1 shfl).
//   p_t = 2^-k * [ mask ? exp(e_t) .* (E p_{t-1}) : p_{t-1} ]
// with k = exponent(p_{t-1,0}) (exact power-of-2 rescale, logged as int K).
// Emissions stream through an 8-deep cp.async smem ring (6-step lookahead);
// masks fully preloaded to smem. No global access on the recursion chain.
// Warp 4: gold-path score with per-batch local ys dtype detection.
// ---------------------------------------------------------------------------
__global__ void __launch_bounds__(160, 1) forward_kernel(
    const float* __restrict__ masks, const float* __restrict__ trans,
    const int* __restrict__ ys32, float* __restrict__ out)
{
    const int b = blockIdx.x;
    const int tid = threadIdx.x;

    __shared__ float p_sm[2][CT];
    __shared__ int   k_sm[2];
    __shared__ float msk[LL];
    __shared__ __align__(16) float ring[8][CT];

    // ---------------- gold warp (warp 4) ----------------
    if (tid >= 128) {
        const int l = tid - 128;
        // local dtype detect: window [b*1024, b*1024+1024) int32 words is
        // in-bounds under both interpretations. int64 => odd words all 0.
        const int* wnd = ys32 + (size_t)b * LL;
        int v = 0;
        for (int idx = l; idx < 512; idx += 32) v |= wnd[2 * idx + 1];
        #pragma unroll
        for (int o = 16; o; o >>= 1) v |= __shfl_xor_sync(0xffffffffu, v, o);
        const int stride = (v == 0) ? 2 : 1;

        const int* yb = ys32 + (size_t)b * LL * stride;
        const float* mb = masks + (size_t)b * LL;
        float local = 0.f, mloc = 0.f;
        for (int t = l; t < LL; t += 32) {
            int y  = yb[t * stride];
            int yp = t ? yb[(t - 1) * stride] : START_TAG;
            y  = min(max(y,  0), CT - 1);
            yp = min(max(yp, 0), C - 1);
            float mk = mb[t];
            local += (trans[y * C + yp] + g_feats[((size_t)b * LL + t) * CT + y]) * mk;
            mloc  += mk;
        }
        #pragma unroll
        for (int o = 16; o; o >>= 1) {
            local += __shfl_xor_sync(0xffffffffu, local, o);
            mloc  += __shfl_xor_sync(0xffffffffu, mloc,  o);
        }
        if (l == 0) {
            int len = (int)(mloc + 0.5f);
            int last = (len > 0) ? yb[(len - 1) * stride] : START_TAG;
            last = min(max(last, 0), C - 1);
            out[NB + b] = local + trans[STOP_TAG * C + last];
        }
        return;
    }

    // ---------------- recursion warps ----------------
    const int i = tid >> 1;     // tag 0..63
    const int q = tid & 1;      // half
    const int j0 = q * 32;

    float E[32];
    #pragma unroll
    for (int jj = 0; jj < 32; ++jj)
        E[jj] = expf(trans[i * C + (j0 + jj)]);

    const float* fb = g_feats + (size_t)b * LL * CT;
    const float* mb = masks + (size_t)b * LL;

    // preload all masks into smem
    for (int idx = tid; idx < LL; idx += 128) msk[idx] = mb[idx];

    // fold step 0: p_0,i = exp(T[i,START] + emit_0[i])  (mask_0-guarded)
    if (q == 0) {
        float mk0 = mb[0];
        float s0 = (mk0 != 0.f) ? (trans[i * C + START_TAG] + fb[i]) : IMPOSSIBLE_F;
        p_sm[0][i] = expf(s0);
    }
    if (tid == 0) { k_sm[0] = 0; k_sm[1] = 0; }

    // cp.async ring prologue: stages for t = 1..6
    unsigned ring_u32 = (unsigned)__cvta_generic_to_shared(&ring[0][0]);
    if (tid < 16) {
        #pragma unroll
        for (int s = 1; s <= 6; ++s) {
            CP_ASYNC16(ring_u32 + (unsigned)((s & 7) * 256 + tid * 16),
                       fb + (size_t)s * CT + tid * 4);
            CP_COMMIT();
        }
    }

    int ktot = 0;
    int buf = 0;
    for (int t = 1; t < LL; ++t) {
        if (tid < 16) {
            if (t + 6 < LL)
                CP_ASYNC16(ring_u32 + (unsigned)(((t + 6) & 7) * 256 + tid * 16),
                           fb + (size_t)(t + 6) * CT + tid * 4);
            CP_COMMIT();
            CP_WAIT6();          // ring slot for step t is complete
        }
        asm volatile("bar.sync 1, 128;" ::: "memory");  // publish p, ring, k

        int k = k_sm[buf];
        ktot += k;
        float scale = __int_as_float((unsigned)(127 - k) << 23);  // exact 2^-k

        float e  = ring[t & 7][i];
        float ee = __expf(e);                 // off critical chain
        float mkt = msk[t];
        float pprev = p_sm[buf][i];

        const float* pp = &p_sm[buf][j0];
        float a0 = 0.f, a1 = 0.f, a2 = 0.f, a3 = 0.f;
        #pragma unroll
        for (int jj = 0; jj < 32; jj += 4) {
            a0 = fmaf(E[jj + 0], pp[jj + 0], a0);
            a1 = fmaf(E[jj + 1], pp[jj + 1], a1);
            a2 = fmaf(E[jj + 2], pp[jj + 2], a2);
            a3 = fmaf(E[jj + 3], pp[jj + 3], a3);
        }
        float acc = (a0 + a1) + (a2 + a3);
        acc += __shfl_xor_sync(0xffffffffu, acc, 1);

        float w = (mkt != 0.f) ? acc * ee : pprev;
        w *= scale;

        if (q == 0) p_sm[buf ^ 1][i] = w;
        if (tid == 0) {
            unsigned wb = __float_as_uint(w);
            int kn = wb ? (int)((wb >> 23) & 255u) - 127 : 0;
            k_sm[buf ^ 1] = kn;
        }
        buf ^= 1;
    }

    asm volatile("bar.sync 1, 128;" ::: "memory");

    // final: out = lse_i( log(p_i) + K*ln2 + T[STOP,i] ), in log2 space
    if (tid < 32) {
        float Kf = (float)ktot;
        float v0 = __log2f(p_sm[buf][tid])      + Kf + trans[STOP_TAG * C + tid]      * L2E;
        float v1 = __log2f(p_sm[buf][tid + 32]) + Kf + trans[STOP_TAG * C + tid + 32] * L2E;
        float mx = fmaxf(v0, v1);
        #pragma unroll
        for (int o = 16; o; o >>= 1) mx = fmaxf(mx, __shfl_xor_sync(0xffffffffu, mx, o));
        float sum = exp2f(v0 - mx) + exp2f(v1 - mx);
        #pragma unroll
        for (int o = 16; o; o >>= 1) sum += __shfl_xor_sync(0xffffffffu, sum, o);
        if (tid == 0) out[b] = (mx + __log2f(sum)) * LN2F;
    }
}

extern "C" void kernel_launch(void* const* d_in, const int* in_sizes, int n_in,
                              void* d_out, int out_size)
{
    const float* features = (const float*)d_in[0];
    const int*   ys32     = (const int*)d_in[1];
    const float* masks    = (const float*)d_in[2];
    const float* fc_w     = (const float*)d_in[3];
    const float* fc_b     = (const float*)d_in[4];
    const float* trans    = (const float*)d_in[5];
    float* out = (float*)d_out;

    gemm_kernel<<<256, 256>>>(features, fc_w, fc_b);
    forward_kernel<<<NB, 160>>>(masks, trans, ys32, out);
}